// round 1
// baseline (speedup 1.0000x reference)
#include <cuda_runtime.h>
#include <math.h>

#define N_NODES 20000
#define MPAD    20032          // padded to multiple of 64
#define N_EDGES 320000
#define N_GRAPHS 64
#define IN_FEAT 64
#define HIDDEN  256
#define GRID_F  4
#define NEG_SLOPE 0.01f

// -------- device scratch (no allocations allowed) --------
__device__ __align__(16) float g_H  [MPAD * HIDDEN];        // node features
__device__ __align__(16) float g_AGG[MPAD * HIDDEN];        // aggregated neighbor sums
__device__ __align__(16) float g_WtF[3 * 2048 * HIDDEN];    // transposed fourier weights [l][k][o]
__device__ __align__(16) float g_WtL[320 * HIDDEN];         // transposed line weights [k][o]
__device__ int g_cnt [N_NODES];
__device__ int g_off [N_NODES + 1];
__device__ int g_cur [N_NODES];
__device__ int g_csrc[N_EDGES];

// -------- weight transposes (run every launch; cheap) --------
// W_line [256 out][64 in][5 deg] -> g_WtL[k = i*5+d][o]
__global__ void k_transpose_line(const float* __restrict__ W) {
    int idx = blockIdx.x * 256 + threadIdx.x;
    if (idx >= 320 * HIDDEN) return;
    int o = idx & 255;
    int k = idx >> 8;
    int i = k / 5, d = k - i * 5;
    g_WtL[idx] = W[(o * IN_FEAT + i) * 5 + d];
}

// fourier_coeffs [3][2 cos/sin][256 out][256 in][4 grid] -> g_WtF[l][k = i*8 + (s*4+g)][o]
__global__ void k_transpose_fourier(const float* __restrict__ F) {
    int idx = blockIdx.x * 256 + threadIdx.x;
    if (idx >= 3 * 2048 * HIDDEN) return;
    int o = idx & 255;
    int k = (idx >> 8) & 2047;
    int l = idx >> 19;          // 2048*256 = 2^19
    int i = k >> 3;
    int t = k & 7;
    int s = t >> 2;             // 0 = cos, 1 = sin
    int g = t & 3;              // harmonic g+1
    g_WtF[idx] = F[(((l * 2 + s) * HIDDEN + o) * HIDDEN + i) * GRID_F + g];
}

// -------- CSR build (by dst) --------
__global__ void k_zero_cnt() {
    int i = blockIdx.x * 256 + threadIdx.x;
    if (i < N_NODES) g_cnt[i] = 0;
}
__global__ void k_hist(const int* __restrict__ dst) {
    int e = blockIdx.x * 256 + threadIdx.x;
    if (e < N_EDGES) atomicAdd(&g_cnt[dst[e]], 1);
}
__global__ void k_scan() {  // single block, 1024 threads, 20 elems/thread
    __shared__ int s[1024];
    int tid = threadIdx.x;
    const int CH = 20;
    int base = tid * CH;
    int sum = 0;
    for (int j = 0; j < CH; j++) { int idx = base + j; if (idx < N_NODES) sum += g_cnt[idx]; }
    s[tid] = sum; __syncthreads();
    for (int d = 1; d < 1024; d <<= 1) {
        int v = (tid >= d) ? s[tid - d] : 0;
        __syncthreads();
        s[tid] += v;
        __syncthreads();
    }
    int run = (tid > 0) ? s[tid - 1] : 0;
    for (int j = 0; j < CH; j++) {
        int idx = base + j;
        if (idx < N_NODES) { g_off[idx] = run; g_cur[idx] = run; run += g_cnt[idx]; }
    }
    if (tid == 1023) g_off[N_NODES] = s[1023];
}
__global__ void k_scatter(const int* __restrict__ src, const int* __restrict__ dst) {
    int e = blockIdx.x * 256 + threadIdx.x;
    if (e < N_EDGES) {
        int pos = atomicAdd(&g_cur[dst[e]], 1);
        g_csrc[pos] = src[e];
    }
}

// -------- edge aggregation: agg[n] = sum_{e: dst==n} h[src[e]]  (no atomics) --------
// block = 256 threads = 4 nodes x 64 float4 lanes
__global__ void k_agg() {
    int node = blockIdx.x * 4 + (threadIdx.x >> 6);
    int lane = threadIdx.x & 63;
    float4 acc = make_float4(0.f, 0.f, 0.f, 0.f);
    if (node < N_NODES) {
        int lo = g_off[node], hi = g_off[node + 1];
        const float4* H4 = (const float4*)g_H;
        for (int e = lo; e < hi; e++) {
            int sN = g_csrc[e];
            float4 v = H4[sN * 64 + lane];
            acc.x += v.x; acc.y += v.y; acc.z += v.z; acc.w += v.w;
        }
    }
    ((float4*)g_AGG)[node * 64 + lane] = acc;  // pad rows get zeros
}

// -------- fused activation + GEMM --------
// MODE 0: H = kan_polynomial(X, W_line)          A = powers of X,  K=320  (8 feats * 5 deg / tile)
// MODE 1: H = leakyrelu(fourier(AGG)@W + H)      A = cos/sin(k*AGG), K=2048 (8 feats * 8 trig / tile)
// 64x64 output tile, 256 threads, 4x4 micro-tile, As stored [k][n] so compute reads are float4.
template <int MODE>
__global__ void k_gemm(const float* __restrict__ Asrc, int layer) {
    constexpr int KT   = (MODE == 0) ? 40 : 64;
    constexpr int NKT  = (MODE == 0) ? 8  : 32;
    constexpr int SRCW = (MODE == 0) ? IN_FEAT : HIDDEN;

    __shared__ __align__(16) float As[KT * 64];
    __shared__ __align__(16) float Bs[KT * 64];

    const float* B = (MODE == 0) ? g_WtL : (g_WtF + (size_t)layer * 2048 * HIDDEN);
    const float* A = (MODE == 0) ? Asrc : g_AGG;

    int tid = threadIdx.x;
    int mb = blockIdx.x * 64;
    int ob = blockIdx.y * 64;
    int ty = tid >> 4, tx = tid & 15;

    float acc[4][4] = {};

    for (int kt = 0; kt < NKT; kt++) {
        int ib = kt * 8;  // 8 input features per k-tile
        // ---- A tile fill: compute activations on the fly ----
        for (int p = tid; p < 64 * 8; p += 256) {
            int i = p & 7, n = p >> 3;
            int row = mb + n;
            float a = (row < N_NODES) ? A[row * SRCW + ib + i] : 0.f;
            if (MODE == 0) {
                float pw = 1.f;
                #pragma unroll
                for (int v = 0; v < 5; v++) { As[(i * 5 + v) * 64 + n] = pw; pw *= a; }
            } else {
                float s1, c1;
                sincosf(a, &s1, &c1);
                float ck = c1, sk = s1;
                As[(i * 8 + 0) * 64 + n] = ck;
                As[(i * 8 + 4) * 64 + n] = sk;
                #pragma unroll
                for (int g = 1; g < 4; g++) {   // exact angle-addition recurrence
                    float c2 = ck * c1 - sk * s1;
                    float s2 = sk * c1 + ck * s1;
                    ck = c2; sk = s2;
                    As[(i * 8 + g) * 64 + n]     = ck;
                    As[(i * 8 + 4 + g) * 64 + n] = sk;
                }
            }
        }
        // ---- B tile fill (coalesced float4) ----
        const float4* B4 = (const float4*)(B + (size_t)(kt * KT) * HIDDEN + ob);
        for (int q = tid; q < KT * 16; q += 256) {
            int kk = q >> 4, oo = q & 15;
            ((float4*)Bs)[kk * 16 + oo] = B4[kk * (HIDDEN / 4) + oo];
        }
        __syncthreads();
        // ---- compute ----
        #pragma unroll 8
        for (int kk = 0; kk < KT; kk++) {
            float4 a4 = ((const float4*)As)[kk * 16 + ty];
            float4 b4 = ((const float4*)Bs)[kk * 16 + tx];
            float av[4] = {a4.x, a4.y, a4.z, a4.w};
            float bv[4] = {b4.x, b4.y, b4.z, b4.w};
            #pragma unroll
            for (int jy = 0; jy < 4; jy++)
                #pragma unroll
                for (int jx = 0; jx < 4; jx++)
                    acc[jy][jx] += av[jy] * bv[jx];
        }
        __syncthreads();
    }
    // ---- epilogue ----
    #pragma unroll
    for (int jy = 0; jy < 4; jy++) {
        int r = mb + ty * 4 + jy;
        if (r >= N_NODES) continue;
        #pragma unroll
        for (int jx = 0; jx < 4; jx++) {
            int c = ob + tx * 4 + jx;
            float v = acc[jy][jx];
            if (MODE == 1) {
                v += g_H[r * HIDDEN + c];               // residual
                v = (v > 0.f) ? v : v * NEG_SLOPE;      // leaky relu
            }
            g_H[r * HIDDEN + c] = v;
        }
    }
}

// -------- pooling + readout (graph_ids sorted -> binary search segments) --------
__device__ __forceinline__ int lbound(const int* a, int n, int v) {
    int lo = 0, hi = n;
    while (lo < hi) { int m = (lo + hi) >> 1; if (a[m] < v) lo = m + 1; else hi = m; }
    return lo;
}
__global__ void k_pool(const int* __restrict__ gid, const float* __restrict__ Wout,
                       const float* __restrict__ bout, float* __restrict__ out) {
    int g = blockIdx.x;
    int f = threadIdx.x;  // 256
    int lo = lbound(gid, N_NODES, g);
    int hi = lbound(gid, N_NODES, g + 1);
    float acc = 0.f;
    for (int n = lo; n < hi; n++) acc += g_H[n * HIDDEN + f];
    float cnt = (float)(hi - lo);
    float y = acc / fmaxf(cnt, 1.f);
    // degree-1 KAN readout: W[0,f,0]*1 + W[0,f,1]*y
    float contrib = Wout[f * 2] + Wout[f * 2 + 1] * y;
    __shared__ float red[256];
    red[f] = contrib; __syncthreads();
    for (int st = 128; st > 0; st >>= 1) {
        if (f < st) red[f] += red[f + st];
        __syncthreads();
    }
    if (f == 0) out[g] = 1.f / (1.f + expf(-(red[0] + bout[0])));
}

// -------- launch --------
extern "C" void kernel_launch(void* const* d_in, const int* in_sizes, int n_in,
                              void* d_out, int out_size) {
    const float* h      = (const float*)d_in[0];
    const int*   src    = (const int*)  d_in[1];
    const int*   dst    = (const int*)  d_in[2];
    const int*   gid    = (const int*)  d_in[3];
    const float* W_line = (const float*)d_in[4];
    const float* fc     = (const float*)d_in[5];
    const float* W_out  = (const float*)d_in[6];
    const float* b_out  = (const float*)d_in[7];
    float* out = (float*)d_out;

    k_transpose_line   <<<(320 * HIDDEN + 255) / 256, 256>>>(W_line);
    k_transpose_fourier<<<(3 * 2048 * HIDDEN + 255) / 256, 256>>>(fc);

    k_zero_cnt<<<(N_NODES + 255) / 256, 256>>>();
    k_hist    <<<(N_EDGES + 255) / 256, 256>>>(dst);
    k_scan    <<<1, 1024>>>();
    k_scatter <<<(N_EDGES + 255) / 256, 256>>>(src, dst);

    dim3 gg(MPAD / 64, HIDDEN / 64);
    k_gemm<0><<<gg, 256>>>(h, 0);
    for (int l = 0; l < 3; l++) {
        k_agg    <<<MPAD / 4, 256>>>();
        k_gemm<1><<<gg, 256>>>(nullptr, l);
    }
    k_pool<<<N_GRAPHS, 256>>>(gid, W_out, b_out, out);
}

// round 5
// speedup vs baseline: 1.3120x; 1.3120x over previous
#include <cuda_runtime.h>
#include <math.h>
#include <stdint.h>

#define N_NODES 20000
#define MPAD    20096          // multiple of 128
#define N_EDGES 320000
#define N_GRAPHS 64
#define IN_FEAT 64
#define HIDDEN  256
#define GRID_F  4
#define NEG_SLOPE 0.01f

#define NCH_F 64               // fourier K=2048 -> 64 chunks of 32
#define NCH_L 16               // line  K=512 (padded) -> 16 chunks of 32
#define KSTR  136              // k-row stride in floats (conflict-free lds)
#define CHFLOATS (32 * KSTR)   // 4352 floats per tile (one of hi/lo)

// -------- device scratch --------
__device__ __align__(16) float g_H  [MPAD * HIDDEN];
__device__ __align__(16) float g_AGG[MPAD * HIDDEN];
// per (layer, nblock, chunk): [hi tile CHFLOATS][lo tile CHFLOATS]
__device__ __align__(16) float g_WtF[3 * 2 * NCH_F * 2 * CHFLOATS];
__device__ __align__(16) float g_WtL[2 * NCH_L * 2 * CHFLOATS];
__device__ int g_cnt [N_NODES];
__device__ int g_off [N_NODES + 1];
__device__ int g_cur [N_NODES];
__device__ int g_csrc[N_EDGES];

__device__ __forceinline__ float to_tf32(float x) {
    float r; asm("cvt.rna.tf32.f32 %0, %1;" : "=f"(r) : "f"(x)); return r;
}
__device__ __forceinline__ void mma_tf32(float* d, const uint32_t* a, const uint32_t* b) {
    asm volatile(
        "mma.sync.aligned.m16n8k8.row.col.f32.tf32.tf32.f32 "
        "{%0,%1,%2,%3}, {%4,%5,%6,%7}, {%8,%9}, {%0,%1,%2,%3};"
        : "+f"(d[0]), "+f"(d[1]), "+f"(d[2]), "+f"(d[3])
        : "r"(a[0]), "r"(a[1]), "r"(a[2]), "r"(a[3]), "r"(b[0]), "r"(b[1]));
}

// -------- weight prep: transpose + split hi/lo + pad --------
__global__ void k_prep_fourier(const float* __restrict__ F) {
    int idx = blockIdx.x * 256 + threadIdx.x;
    if (idx >= 3 * 2 * NCH_F * CHFLOATS) return;
    int n  = idx % KSTR;
    int t  = idx / KSTR;
    int kk = t & 31; t >>= 5;
    int c  = t % NCH_F; t /= NCH_F;
    int nb = t & 1;
    int l  = t >> 1;
    float v = 0.f;
    if (n < 128) {
        int i = c * 4 + (kk >> 3);
        int s = (kk >> 2) & 1;
        int g = kk & 3;
        int ng = nb * 128 + n;
        v = F[(((l * 2 + s) * HIDDEN + ng) * HIDDEN + i) * GRID_F + g];
    }
    float hi = to_tf32(v);
    float lo = to_tf32(v - hi);
    size_t base = ((size_t)((l * 2 + nb) * NCH_F + c)) * (2 * CHFLOATS) + kk * KSTR + n;
    g_WtF[base]            = hi;
    g_WtF[base + CHFLOATS] = lo;
}
__global__ void k_prep_line(const float* __restrict__ W) {
    int idx = blockIdx.x * 256 + threadIdx.x;
    if (idx >= 2 * NCH_L * CHFLOATS) return;
    int n  = idx % KSTR;
    int t  = idx / KSTR;
    int kk = t & 31; t >>= 5;
    int c  = t % NCH_L;
    int nb = t / NCH_L;
    float v = 0.f;
    int d = kk & 7;
    if (n < 128 && d <= GRID_F) {
        int i = c * 4 + (kk >> 3);
        int ng = nb * 128 + n;
        v = W[(ng * IN_FEAT + i) * (GRID_F + 1) + d];
    }
    float hi = to_tf32(v);
    float lo = to_tf32(v - hi);
    size_t base = ((size_t)(nb * NCH_L + c)) * (2 * CHFLOATS) + kk * KSTR + n;
    g_WtL[base]            = hi;
    g_WtL[base + CHFLOATS] = lo;
}

// -------- CSR build --------
__global__ void k_zero_cnt() {
    int i = blockIdx.x * 256 + threadIdx.x;
    if (i < N_NODES) g_cnt[i] = 0;
}
__global__ void k_hist(const int* __restrict__ dst) {
    int e = blockIdx.x * 256 + threadIdx.x;
    if (e < N_EDGES) atomicAdd(&g_cnt[dst[e]], 1);
}
__global__ void k_scan() {
    __shared__ int s[1024];
    int tid = threadIdx.x;
    const int CH = 20;
    int base = tid * CH;
    int sum = 0;
    for (int j = 0; j < CH; j++) { int idx = base + j; if (idx < N_NODES) sum += g_cnt[idx]; }
    s[tid] = sum; __syncthreads();
    for (int d = 1; d < 1024; d <<= 1) {
        int v = (tid >= d) ? s[tid - d] : 0;
        __syncthreads();
        s[tid] += v;
        __syncthreads();
    }
    int run = (tid > 0) ? s[tid - 1] : 0;
    for (int j = 0; j < CH; j++) {
        int idx = base + j;
        if (idx < N_NODES) { g_off[idx] = run; g_cur[idx] = run; run += g_cnt[idx]; }
    }
    if (tid == 1023) g_off[N_NODES] = s[1023];
}
__global__ void k_scatter(const int* __restrict__ src, const int* __restrict__ dst) {
    int e = blockIdx.x * 256 + threadIdx.x;
    if (e < N_EDGES) {
        int pos = atomicAdd(&g_cur[dst[e]], 1);
        g_csrc[pos] = src[e];
    }
}

// -------- edge aggregation (CSR gather, no atomics) --------
__global__ void k_agg() {
    int node = blockIdx.x * 4 + (threadIdx.x >> 6);
    int lane = threadIdx.x & 63;
    float4 acc = make_float4(0.f, 0.f, 0.f, 0.f);
    if (node < N_NODES) {
        int lo = g_off[node], hi = g_off[node + 1];
        const float4* H4 = (const float4*)g_H;
        for (int e = lo; e < hi; e++) {
            int sN = g_csrc[e];
            float4 v = H4[sN * 64 + lane];
            acc.x += v.x; acc.y += v.y; acc.z += v.z; acc.w += v.w;
        }
    }
    ((float4*)g_AGG)[node * 64 + lane] = acc;
}

// -------- 3xTF32 mma.sync fused activation + GEMM --------
// CTA 128x128, BK=32, 8 warps 2x4, warp tile 64x32.
// SMEM (dynamic, floats): As_hi @0, As_lo @4352, Bs_hi @8704, Bs_lo @13056
#define SM_FLOATS (4 * CHFLOATS)
#define SM_BYTES  (SM_FLOATS * 4)

template <int MODE>
__global__ void __launch_bounds__(256, 2) k_mma(const float* __restrict__ X, int layer) {
    extern __shared__ float sm[];
    float* As_hi = sm;
    float* As_lo = sm + CHFLOATS;
    float* Bs_hi = sm + 2 * CHFLOATS;
    float* Bs_lo = sm + 3 * CHFLOATS;

    const int NCH  = (MODE == 0) ? NCH_L : NCH_F;
    const int srcw = (MODE == 0) ? IN_FEAT : HIDDEN;
    const float* A = (MODE == 0) ? X : g_AGG;
    const float* Bsrc = (MODE == 0)
        ? (g_WtL + (size_t)(blockIdx.y * NCH_L) * (2 * CHFLOATS))
        : (g_WtF + (size_t)((layer * 2 + blockIdx.y) * NCH_F) * (2 * CHFLOATS));

    int tid  = threadIdx.x;
    int lane = tid & 31;
    int wid  = tid >> 5;
    int wm = (wid >> 2) * 64;
    int wn = (wid & 3) * 32;
    int mb = blockIdx.x * 128;
    int ob = blockIdx.y * 128;

    int row = tid & 127;
    int f2  = (tid >> 7) * 2;
    int gr  = mb + row;

    float d[4][4][4];
    #pragma unroll
    for (int mf = 0; mf < 4; mf++)
        #pragma unroll
        for (int nf = 0; nf < 4; nf++)
            #pragma unroll
            for (int q = 0; q < 4; q++) d[mf][nf][q] = 0.f;

    for (int c = 0; c < NCH; c++) {
        __syncthreads();
        // ---- A fill: activations, split hi/lo ----
        #pragma unroll
        for (int ff = 0; ff < 2; ff++) {
            int lf = f2 + ff;
            float a = 0.f;
            if (MODE == 1 || gr < N_NODES) a = A[(size_t)gr * srcw + c * 4 + lf];
            float vals[8];
            if (MODE == 0) {
                float pw = 1.f;
                #pragma unroll
                for (int v = 0; v < 5; v++) { vals[v] = pw; pw *= a; }
                vals[5] = 0.f; vals[6] = 0.f; vals[7] = 0.f;
            } else {
                float s1, c1;
                sincosf(a, &s1, &c1);
                float ck = c1, sk = s1;
                vals[0] = ck; vals[4] = sk;
                #pragma unroll
                for (int g = 1; g < 4; g++) {
                    float c2 = ck * c1 - sk * s1;
                    float s2 = sk * c1 + ck * s1;
                    ck = c2; sk = s2;
                    vals[g] = ck; vals[4 + g] = sk;
                }
            }
            #pragma unroll
            for (int j = 0; j < 8; j++) {
                float hi = to_tf32(vals[j]);
                float lo = to_tf32(vals[j] - hi);
                As_hi[(lf * 8 + j) * KSTR + row] = hi;
                As_lo[(lf * 8 + j) * KSTR + row] = lo;
            }
        }
        // ---- B fill: contiguous float4 copy (hi then lo, adjacent in global) ----
        {
            const float4* sp = (const float4*)(Bsrc + (size_t)c * (2 * CHFLOATS));
            float4* dp = (float4*)Bs_hi;  // Bs_hi and Bs_lo are contiguous
            #pragma unroll
            for (int q = 0; q < 9; q++) {
                int p = tid + q * 256;
                if (p < 2 * CHFLOATS / 4) dp[p] = sp[p];
            }
        }
        __syncthreads();
        // ---- compute: 4 k-steps of 8, 3 mma terms each ----
        #pragma unroll
        for (int ks = 0; ks < 4; ks++) {
            int kr = ks * 8 + (lane & 3);
            int aoff  = kr * KSTR + wm + (lane >> 2);
            int boff  = kr * KSTR + wn + (lane >> 2);
            uint32_t ah[4][4], al[4][4], bh[4][2], bl[4][2];
            #pragma unroll
            for (int mf = 0; mf < 4; mf++) {
                ah[mf][0] = ((const uint32_t*)As_hi)[aoff + mf * 16];
                ah[mf][1] = ((const uint32_t*)As_hi)[aoff + mf * 16 + 8];
                ah[mf][2] = ((const uint32_t*)As_hi)[aoff + 4 * KSTR + mf * 16];
                ah[mf][3] = ((const uint32_t*)As_hi)[aoff + 4 * KSTR + mf * 16 + 8];
                al[mf][0] = ((const uint32_t*)As_lo)[aoff + mf * 16];
                al[mf][1] = ((const uint32_t*)As_lo)[aoff + mf * 16 + 8];
                al[mf][2] = ((const uint32_t*)As_lo)[aoff + 4 * KSTR + mf * 16];
                al[mf][3] = ((const uint32_t*)As_lo)[aoff + 4 * KSTR + mf * 16 + 8];
            }
            #pragma unroll
            for (int nf = 0; nf < 4; nf++) {
                bh[nf][0] = ((const uint32_t*)Bs_hi)[boff + nf * 8];
                bh[nf][1] = ((const uint32_t*)Bs_hi)[boff + 4 * KSTR + nf * 8];
                bl[nf][0] = ((const uint32_t*)Bs_lo)[boff + nf * 8];
                bl[nf][1] = ((const uint32_t*)Bs_lo)[boff + 4 * KSTR + nf * 8];
            }
            #pragma unroll
            for (int mf = 0; mf < 4; mf++)
                #pragma unroll
                for (int nf = 0; nf < 4; nf++) {
                    mma_tf32(d[mf][nf], al[mf], bh[nf]);   // lo*hi
                    mma_tf32(d[mf][nf], ah[mf], bl[nf]);   // hi*lo
                    mma_tf32(d[mf][nf], ah[mf], bh[nf]);   // hi*hi
                }
        }
    }

    // ---- epilogue ----
    int r0 = lane >> 2;
    int c0 = 2 * (lane & 3);
    #pragma unroll
    for (int mf = 0; mf < 4; mf++) {
        #pragma unroll
        for (int half = 0; half < 2; half++) {
            int rg = mb + wm + mf * 16 + r0 + half * 8;
            float* Hrow = g_H + (size_t)rg * HIDDEN + ob + wn + c0;
            #pragma unroll
            for (int nf = 0; nf < 4; nf++) {
                float vx = d[mf][nf][half * 2];
                float vy = d[mf][nf][half * 2 + 1];
                float2* p = (float2*)(Hrow + nf * 8);
                if (MODE == 1) {
                    float2 h0 = *p;
                    vx += h0.x; vy += h0.y;
                    vx = (vx > 0.f) ? vx : vx * NEG_SLOPE;
                    vy = (vy > 0.f) ? vy : vy * NEG_SLOPE;
                }
                *p = make_float2(vx, vy);
            }
        }
    }
}

// -------- pooling + readout --------
__device__ __forceinline__ int lbound(const int* a, int n, int v) {
    int lo = 0, hi = n;
    while (lo < hi) { int m = (lo + hi) >> 1; if (a[m] < v) lo = m + 1; else hi = m; }
    return lo;
}
__global__ void k_pool(const int* __restrict__ gid, const float* __restrict__ Wout,
                       const float* __restrict__ bout, float* __restrict__ out) {
    int g = blockIdx.x;
    int f = threadIdx.x;
    int lo = lbound(gid, N_NODES, g);
    int hi = lbound(gid, N_NODES, g + 1);
    float acc = 0.f;
    for (int n = lo; n < hi; n++) acc += g_H[(size_t)n * HIDDEN + f];
    float cnt = (float)(hi - lo);
    float y = acc / fmaxf(cnt, 1.f);
    float contrib = Wout[f * 2] + Wout[f * 2 + 1] * y;
    __shared__ float red[256];
    red[f] = contrib; __syncthreads();
    for (int st = 128; st > 0; st >>= 1) {
        if (f < st) red[f] += red[f + st];
        __syncthreads();
    }
    if (f == 0) out[g] = 1.f / (1.f + expf(-(red[0] + bout[0])));
}

// -------- launch --------
extern "C" void kernel_launch(void* const* d_in, const int* in_sizes, int n_in,
                              void* d_out, int out_size) {
    const float* h      = (const float*)d_in[0];
    const int*   src    = (const int*)  d_in[1];
    const int*   dst    = (const int*)  d_in[2];
    const int*   gid    = (const int*)  d_in[3];
    const float* W_line = (const float*)d_in[4];
    const float* fc     = (const float*)d_in[5];
    const float* W_out  = (const float*)d_in[6];
    const float* b_out  = (const float*)d_in[7];
    float* out = (float*)d_out;

    static int smem_set = 0;
    if (!smem_set) {
        cudaFuncSetAttribute(k_mma<0>, cudaFuncAttributeMaxDynamicSharedMemorySize, SM_BYTES);
        cudaFuncSetAttribute(k_mma<1>, cudaFuncAttributeMaxDynamicSharedMemorySize, SM_BYTES);
        smem_set = 1;
    }

    k_prep_line   <<<(2 * NCH_L * CHFLOATS + 255) / 256, 256>>>(W_line);
    k_prep_fourier<<<(3 * 2 * NCH_F * CHFLOATS + 255) / 256, 256>>>(fc);

    k_zero_cnt<<<(N_NODES + 255) / 256, 256>>>();
    k_hist    <<<(N_EDGES + 255) / 256, 256>>>(dst);
    k_scan    <<<1, 1024>>>();
    k_scatter <<<(N_EDGES + 255) / 256, 256>>>(src, dst);

    dim3 gg(MPAD / 128, 2);
    k_mma<0><<<gg, 256, SM_BYTES>>>(h, 0);
    for (int l = 0; l < 3; l++) {
        k_agg  <<<MPAD / 4, 256>>>();
        k_mma<1><<<gg, 256, SM_BYTES>>>(nullptr, l);
    }
    k_pool<<<N_GRAPHS, 256>>>(gid, W_out, b_out, out);
}

// round 6
// speedup vs baseline: 2.1210x; 1.6166x over previous
#include <cuda_runtime.h>
#include <cuda_fp16.h>
#include <math.h>
#include <stdint.h>

#define N_NODES 20000
#define MPAD    20096          // multiple of 128
#define N_EDGES 320000
#define N_GRAPHS 64
#define IN_FEAT 64
#define HIDDEN  256
#define GRID_F  4
#define NEG_SLOPE 0.01f

#define NCH_F 64               // fourier K=2048 -> 64 chunks of 32
#define NCH_L 16               // line  K=512 (padded) -> 16 chunks of 32
#define KSTR  136              // row stride in uint32 (conflict-free lds)
#define TILE_U32 (16 * KSTR)   // 16 kpairs x 136 = 2176 u32 per tile

// -------- device scratch --------
__device__ __align__(16) float g_H  [MPAD * HIDDEN];
__device__ __align__(16) float g_AGG[MPAD * HIDDEN];
// per (layer, nblock, chunk): [hi tile][lo tile], each TILE_U32 of packed fp16x2
__device__ __align__(16) uint32_t g_WtF32[3 * 2 * NCH_F * 2 * TILE_U32];
__device__ __align__(16) uint32_t g_WtL32[2 * NCH_L * 2 * TILE_U32];
__device__ int g_cnt [N_NODES];
__device__ int g_off [N_NODES + 1];
__device__ int g_cur [N_NODES];
__device__ int g_csrc[N_EDGES];

__device__ __forceinline__ uint32_t pack_hi(float v0, float v1, float& l0, float& l1) {
    __half h0 = __float2half_rn(v0), h1 = __float2half_rn(v1);
    l0 = v0 - __half2float(h0);
    l1 = v1 - __half2float(h1);
    return (uint32_t)__half_as_ushort(h0) | ((uint32_t)__half_as_ushort(h1) << 16);
}
__device__ __forceinline__ uint32_t pack_lo(float l0, float l1) {
    return (uint32_t)__half_as_ushort(__float2half_rn(l0))
         | ((uint32_t)__half_as_ushort(__float2half_rn(l1)) << 16);
}
__device__ __forceinline__ void mma_f16(float* d, const uint32_t* a, const uint32_t* b) {
    asm volatile(
        "mma.sync.aligned.m16n8k16.row.col.f32.f16.f16.f32 "
        "{%0,%1,%2,%3}, {%4,%5,%6,%7}, {%8,%9}, {%0,%1,%2,%3};"
        : "+f"(d[0]), "+f"(d[1]), "+f"(d[2]), "+f"(d[3])
        : "r"(a[0]), "r"(a[1]), "r"(a[2]), "r"(a[3]), "r"(b[0]), "r"(b[1]));
}

// -------- weight prep: transpose + fp16 split + pack k-pairs --------
// Per tile element: kpair p (0..15) = lf*4 + tq; k slots j = tq*2, tq*2+1 (j = s*4+g)
__global__ void k_prep_fourier(const float* __restrict__ F) {
    int idx = blockIdx.x * 256 + threadIdx.x;
    if (idx >= 3 * 2 * NCH_F * TILE_U32) return;
    int n = idx % KSTR;
    int t = idx / KSTR;
    int p = t & 15; t >>= 4;
    int c = t % NCH_F; t /= NCH_F;
    int nb = t & 1;
    int l  = t >> 1;
    float v0 = 0.f, v1 = 0.f;
    if (n < 128) {
        int lf = p >> 2, tq = p & 3;
        int i  = c * 4 + lf;
        int s0 = tq >> 1;
        int g0 = (tq & 1) * 2;
        int ng = nb * 128 + n;
        const float* base = F + (((size_t)(l * 2 + s0) * HIDDEN + ng) * HIDDEN + i) * GRID_F;
        v0 = base[g0];
        v1 = base[g0 + 1];
    }
    float l0, l1;
    uint32_t hp = pack_hi(v0, v1, l0, l1);
    uint32_t lp = pack_lo(l0, l1);
    size_t base = ((size_t)((l * 2 + nb) * NCH_F + c)) * (2 * TILE_U32) + p * KSTR + n;
    g_WtF32[base]            = hp;
    g_WtF32[base + TILE_U32] = lp;
}
__global__ void k_prep_line(const float* __restrict__ W) {
    int idx = blockIdx.x * 256 + threadIdx.x;
    if (idx >= 2 * NCH_L * TILE_U32) return;
    int n = idx % KSTR;
    int t = idx / KSTR;
    int p = t & 15; t >>= 4;
    int c = t % NCH_L;
    int nb = t / NCH_L;
    float v0 = 0.f, v1 = 0.f;
    if (n < 128) {
        int lf = p >> 2, tq = p & 3;
        int i  = c * 4 + lf;
        int d0 = tq * 2;
        int ng = nb * 128 + n;
        const float* base = W + ((size_t)ng * IN_FEAT + i) * (GRID_F + 1);
        if (d0     <= GRID_F) v0 = base[d0];
        if (d0 + 1 <= GRID_F) v1 = base[d0 + 1];
    }
    float l0, l1;
    uint32_t hp = pack_hi(v0, v1, l0, l1);
    uint32_t lp = pack_lo(l0, l1);
    size_t base = ((size_t)(nb * NCH_L + c)) * (2 * TILE_U32) + p * KSTR + n;
    g_WtL32[base]            = hp;
    g_WtL32[base + TILE_U32] = lp;
}

// -------- CSR build --------
__global__ void k_zero_cnt() {
    int i = blockIdx.x * 256 + threadIdx.x;
    if (i < N_NODES) g_cnt[i] = 0;
}
__global__ void k_hist(const int* __restrict__ dst) {
    int e = blockIdx.x * 256 + threadIdx.x;
    if (e < N_EDGES) atomicAdd(&g_cnt[dst[e]], 1);
}
__global__ void k_scan() {
    __shared__ int s[1024];
    int tid = threadIdx.x;
    const int CH = 20;
    int base = tid * CH;
    int sum = 0;
    for (int j = 0; j < CH; j++) { int idx = base + j; if (idx < N_NODES) sum += g_cnt[idx]; }
    s[tid] = sum; __syncthreads();
    for (int d = 1; d < 1024; d <<= 1) {
        int v = (tid >= d) ? s[tid - d] : 0;
        __syncthreads();
        s[tid] += v;
        __syncthreads();
    }
    int run = (tid > 0) ? s[tid - 1] : 0;
    for (int j = 0; j < CH; j++) {
        int idx = base + j;
        if (idx < N_NODES) { g_off[idx] = run; g_cur[idx] = run; run += g_cnt[idx]; }
    }
    if (tid == 1023) g_off[N_NODES] = s[1023];
}
__global__ void k_scatter(const int* __restrict__ src, const int* __restrict__ dst) {
    int e = blockIdx.x * 256 + threadIdx.x;
    if (e < N_EDGES) {
        int pos = atomicAdd(&g_cur[dst[e]], 1);
        g_csrc[pos] = src[e];
    }
}

// -------- edge aggregation (CSR gather, no atomics) --------
__global__ void k_agg() {
    int node = blockIdx.x * 4 + (threadIdx.x >> 6);
    int lane = threadIdx.x & 63;
    float4 acc = make_float4(0.f, 0.f, 0.f, 0.f);
    if (node < N_NODES) {
        int lo = g_off[node], hi = g_off[node + 1];
        const float4* H4 = (const float4*)g_H;
        for (int e = lo; e < hi; e++) {
            int sN = g_csrc[e];
            float4 v = H4[sN * 64 + lane];
            acc.x += v.x; acc.y += v.y; acc.z += v.z; acc.w += v.w;
        }
    }
    ((float4*)g_AGG)[node * 64 + lane] = acc;
}

// -------- fp16 split-2 3-term mma.sync GEMM, fused activations --------
// CTA 128x128, BK=32 (16 kpairs), 8 warps 2x4, warp tile 64x32.
// SMEM: As_hi | As_lo | Bs_hi | Bs_lo, each [16 kpair][KSTR] uint32 (fp16x2 along k).
template <int MODE>
__global__ void __launch_bounds__(256, 2) k_mma(const float* __restrict__ X, int layer) {
    __shared__ uint32_t sm[4 * TILE_U32];
    uint32_t* As_hi = sm;
    uint32_t* As_lo = sm + TILE_U32;
    uint32_t* Bs_hi = sm + 2 * TILE_U32;
    uint32_t* Bs_lo = sm + 3 * TILE_U32;

    const int NCH  = (MODE == 0) ? NCH_L : NCH_F;
    const int srcw = (MODE == 0) ? IN_FEAT : HIDDEN;
    const float* A = (MODE == 0) ? X : g_AGG;
    const uint32_t* Bsrc = (MODE == 0)
        ? (g_WtL32 + (size_t)(blockIdx.y * NCH_L) * (2 * TILE_U32))
        : (g_WtF32 + (size_t)((layer * 2 + blockIdx.y) * NCH_F) * (2 * TILE_U32));

    int tid  = threadIdx.x;
    int lane = tid & 31;
    int wid  = tid >> 5;
    int wm = (wid >> 2) * 64;
    int wn = (wid & 3) * 32;
    int mb = blockIdx.x * 128;
    int ob = blockIdx.y * 128;

    int row = tid & 127;
    int f2  = (tid >> 7) * 2;
    int gr  = mb + row;

    float d[4][4][4];
    #pragma unroll
    for (int mf = 0; mf < 4; mf++)
        #pragma unroll
        for (int nf = 0; nf < 4; nf++)
            #pragma unroll
            for (int q = 0; q < 4; q++) d[mf][nf][q] = 0.f;

    for (int c = 0; c < NCH; c++) {
        __syncthreads();
        // ---- A fill: 2 (row, feature) activations, split + pack ----
        #pragma unroll
        for (int ff = 0; ff < 2; ff++) {
            int lf = f2 + ff;
            float a = 0.f;
            if (MODE == 1 || gr < N_NODES) a = A[(size_t)gr * srcw + c * 4 + lf];
            float vals[8];
            if (MODE == 0) {
                float pw = 1.f;
                #pragma unroll
                for (int v = 0; v < 5; v++) { vals[v] = pw; pw *= a; }
                vals[5] = 0.f; vals[6] = 0.f; vals[7] = 0.f;
            } else {
                float s1, c1;
                sincosf(a, &s1, &c1);
                float ck = c1, sk = s1;
                vals[0] = ck; vals[4] = sk;
                #pragma unroll
                for (int g = 1; g < 4; g++) {
                    float c2 = ck * c1 - sk * s1;
                    float s2 = sk * c1 + ck * s1;
                    ck = c2; sk = s2;
                    vals[g] = ck; vals[4 + g] = sk;
                }
            }
            #pragma unroll
            for (int t = 0; t < 4; t++) {
                float l0, l1;
                uint32_t hp = pack_hi(vals[2 * t], vals[2 * t + 1], l0, l1);
                uint32_t lp = pack_lo(l0, l1);
                int off = (lf * 4 + t) * KSTR + row;
                As_hi[off] = hp;
                As_lo[off] = lp;
            }
        }
        // ---- B fill: contiguous float4 copy (hi + lo tiles adjacent) ----
        {
            const float4* sp = (const float4*)(Bsrc + (size_t)c * (2 * TILE_U32));
            float4* dp = (float4*)Bs_hi;   // Bs_hi/Bs_lo contiguous
            #pragma unroll
            for (int q = 0; q < 5; q++) {
                int p = tid + q * 256;
                if (p < 2 * TILE_U32 / 4) dp[p] = sp[p];
            }
        }
        __syncthreads();
        // ---- compute: 2 k16 steps, 3 mma terms each ----
        #pragma unroll
        for (int s = 0; s < 2; s++) {
            int kp = s * 8 + (lane & 3);
            int aoff = kp * KSTR + wm + (lane >> 2);
            int boff = kp * KSTR + wn + (lane >> 2);
            uint32_t ah[4][4], al[4][4], bh[4][2], bl[4][2];
            #pragma unroll
            for (int mf = 0; mf < 4; mf++) {
                ah[mf][0] = As_hi[aoff + mf * 16];
                ah[mf][1] = As_hi[aoff + mf * 16 + 8];
                ah[mf][2] = As_hi[aoff + 4 * KSTR + mf * 16];
                ah[mf][3] = As_hi[aoff + 4 * KSTR + mf * 16 + 8];
                al[mf][0] = As_lo[aoff + mf * 16];
                al[mf][1] = As_lo[aoff + mf * 16 + 8];
                al[mf][2] = As_lo[aoff + 4 * KSTR + mf * 16];
                al[mf][3] = As_lo[aoff + 4 * KSTR + mf * 16 + 8];
            }
            #pragma unroll
            for (int nf = 0; nf < 4; nf++) {
                bh[nf][0] = Bs_hi[boff + nf * 8];
                bh[nf][1] = Bs_hi[boff + 4 * KSTR + nf * 8];
                bl[nf][0] = Bs_lo[boff + nf * 8];
                bl[nf][1] = Bs_lo[boff + 4 * KSTR + nf * 8];
            }
            #pragma unroll
            for (int mf = 0; mf < 4; mf++)
                #pragma unroll
                for (int nf = 0; nf < 4; nf++) {
                    mma_f16(d[mf][nf], al[mf], bh[nf]);   // lo*hi
                    mma_f16(d[mf][nf], ah[mf], bl[nf]);   // hi*lo
                    mma_f16(d[mf][nf], ah[mf], bh[nf]);   // hi*hi
                }
        }
    }

    // ---- epilogue: residual + leaky relu (MODE 1) ----
    int r0 = lane >> 2;
    int c0 = 2 * (lane & 3);
    #pragma unroll
    for (int mf = 0; mf < 4; mf++) {
        #pragma unroll
        for (int half = 0; half < 2; half++) {
            int rg = mb + wm + mf * 16 + r0 + half * 8;
            float* Hrow = g_H + (size_t)rg * HIDDEN + ob + wn + c0;
            #pragma unroll
            for (int nf = 0; nf < 4; nf++) {
                float vx = d[mf][nf][half * 2];
                float vy = d[mf][nf][half * 2 + 1];
                float2* p = (float2*)(Hrow + nf * 8);
                if (MODE == 1) {
                    float2 h0 = *p;
                    vx += h0.x; vy += h0.y;
                    vx = (vx > 0.f) ? vx : vx * NEG_SLOPE;
                    vy = (vy > 0.f) ? vy : vy * NEG_SLOPE;
                }
                *p = make_float2(vx, vy);
            }
        }
    }
}

// -------- pooling + readout --------
__device__ __forceinline__ int lbound(const int* a, int n, int v) {
    int lo = 0, hi = n;
    while (lo < hi) { int m = (lo + hi) >> 1; if (a[m] < v) lo = m + 1; else hi = m; }
    return lo;
}
__global__ void k_pool(const int* __restrict__ gid, const float* __restrict__ Wout,
                       const float* __restrict__ bout, float* __restrict__ out) {
    int g = blockIdx.x;
    int f = threadIdx.x;
    int lo = lbound(gid, N_NODES, g);
    int hi = lbound(gid, N_NODES, g + 1);
    float acc = 0.f;
    for (int n = lo; n < hi; n++) acc += g_H[(size_t)n * HIDDEN + f];
    float cnt = (float)(hi - lo);
    float y = acc / fmaxf(cnt, 1.f);
    float contrib = Wout[f * 2] + Wout[f * 2 + 1] * y;
    __shared__ float red[256];
    red[f] = contrib; __syncthreads();
    for (int st = 128; st > 0; st >>= 1) {
        if (f < st) red[f] += red[f + st];
        __syncthreads();
    }
    if (f == 0) out[g] = 1.f / (1.f + expf(-(red[0] + bout[0])));
}

// -------- launch --------
extern "C" void kernel_launch(void* const* d_in, const int* in_sizes, int n_in,
                              void* d_out, int out_size) {
    const float* h      = (const float*)d_in[0];
    const int*   src    = (const int*)  d_in[1];
    const int*   dst    = (const int*)  d_in[2];
    const int*   gid    = (const int*)  d_in[3];
    const float* W_line = (const float*)d_in[4];
    const float* fc     = (const float*)d_in[5];
    const float* W_out  = (const float*)d_in[6];
    const float* b_out  = (const float*)d_in[7];
    float* out = (float*)d_out;

    k_prep_line   <<<(2 * NCH_L * TILE_U32 + 255) / 256, 256>>>(W_line);
    k_prep_fourier<<<(3 * 2 * NCH_F * TILE_U32 + 255) / 256, 256>>>(fc);

    k_zero_cnt<<<(N_NODES + 255) / 256, 256>>>();
    k_hist    <<<(N_EDGES + 255) / 256, 256>>>(dst);
    k_scan    <<<1, 1024>>>();
    k_scatter <<<(N_EDGES + 255) / 256, 256>>>(src, dst);

    dim3 gg(MPAD / 128, 2);
    k_mma<0><<<gg, 256>>>(h, 0);
    for (int l = 0; l < 3; l++) {
        k_agg  <<<MPAD / 4, 256>>>();
        k_mma<1><<<gg, 256>>>(nullptr, l);
    }
    k_pool<<<N_GRAPHS, 256>>>(gid, W_out, b_out, out);
}

// round 8
// speedup vs baseline: 2.4319x; 1.1466x over previous
#include <cuda_runtime.h>
#include <cuda_fp16.h>
#include <math.h>
#include <stdint.h>

#define N_NODES 20000
#define MPAD    20032          // multiple of 64
#define MT      (MPAD / 64)    // 313 M-tiles
#define N_EDGES 320000
#define N_GRAPHS 64
#define IN_FEAT 64
#define HIDDEN  256
#define GRID_F  4
#define NEG_SLOPE 0.01f

#define NCH_F 64               // fourier K=2048 -> 64 chunks of 32
#define NCH_L 16               // line  K=512 (padded) -> 16 chunks of 32
#define KSTR_A 72              // A row stride in u32 (72 mod 32 = 8 -> conflict-free)
#define KSTR_B 136             // B row stride in u32
#define TILE_A (16 * KSTR_A)   // 1152 u32
#define TILE_B (16 * KSTR_B)   // 2176 u32

// -------- device scratch --------
__device__ __align__(16) float g_H  [MPAD * HIDDEN];
__device__ __align__(16) float g_AGG[MPAD * HIDDEN];
// per (layer, nblock, chunk): [hi tile][lo tile], each TILE_B packed fp16x2
__device__ __align__(16) uint32_t g_WtF32[3 * 2 * NCH_F * 2 * TILE_B];
__device__ __align__(16) uint32_t g_WtL32[2 * NCH_L * 2 * TILE_B];
__device__ int g_cnt [N_NODES];
__device__ int g_off [N_NODES + 1];
__device__ int g_cur [N_NODES];
__device__ int g_csrc[N_EDGES];

__device__ __forceinline__ uint32_t pack_hi(float v0, float v1, float& l0, float& l1) {
    __half h0 = __float2half_rn(v0), h1 = __float2half_rn(v1);
    l0 = v0 - __half2float(h0);
    l1 = v1 - __half2float(h1);
    return (uint32_t)__half_as_ushort(h0) | ((uint32_t)__half_as_ushort(h1) << 16);
}
__device__ __forceinline__ uint32_t pack_lo(float l0, float l1) {
    return (uint32_t)__half_as_ushort(__float2half_rn(l0))
         | ((uint32_t)__half_as_ushort(__float2half_rn(l1)) << 16);
}
__device__ __forceinline__ void mma_f16(float* d, const uint32_t* a, const uint32_t* b) {
    asm volatile(
        "mma.sync.aligned.m16n8k16.row.col.f32.f16.f16.f32 "
        "{%0,%1,%2,%3}, {%4,%5,%6,%7}, {%8,%9}, {%0,%1,%2,%3};"
        : "+f"(d[0]), "+f"(d[1]), "+f"(d[2]), "+f"(d[3])
        : "r"(a[0]), "r"(a[1]), "r"(a[2]), "r"(a[3]), "r"(b[0]), "r"(b[1]));
}

// -------- weight prep: transpose + fp16 split + pack k-pairs --------
__global__ void k_prep_fourier(const float* __restrict__ F) {
    int idx = blockIdx.x * 256 + threadIdx.x;
    if (idx >= 3 * 2 * NCH_F * TILE_B) return;
    int n = idx % KSTR_B;
    int t = idx / KSTR_B;
    int p = t & 15; t >>= 4;
    int c = t % NCH_F; t /= NCH_F;
    int nb = t & 1;
    int l  = t >> 1;
    float v0 = 0.f, v1 = 0.f;
    if (n < 128) {
        int lf = p >> 2, tq = p & 3;
        int i  = c * 4 + lf;
        int s0 = tq >> 1;
        int g0 = (tq & 1) * 2;
        int ng = nb * 128 + n;
        const float* base = F + (((size_t)(l * 2 + s0) * HIDDEN + ng) * HIDDEN + i) * GRID_F;
        v0 = base[g0];
        v1 = base[g0 + 1];
    }
    float l0, l1;
    uint32_t hp = pack_hi(v0, v1, l0, l1);
    uint32_t lp = pack_lo(l0, l1);
    size_t base = ((size_t)((l * 2 + nb) * NCH_F + c)) * (2 * TILE_B) + p * KSTR_B + n;
    g_WtF32[base]          = hp;
    g_WtF32[base + TILE_B] = lp;
}
__global__ void k_prep_line(const float* __restrict__ W) {
    int idx = blockIdx.x * 256 + threadIdx.x;
    if (idx >= 2 * NCH_L * TILE_B) return;
    int n = idx % KSTR_B;
    int t = idx / KSTR_B;
    int p = t & 15; t >>= 4;
    int c = t % NCH_L;
    int nb = t / NCH_L;
    float v0 = 0.f, v1 = 0.f;
    if (n < 128) {
        int lf = p >> 2, tq = p & 3;
        int i  = c * 4 + lf;
        int d0 = tq * 2;
        int ng = nb * 128 + n;
        const float* base = W + ((size_t)ng * IN_FEAT + i) * (GRID_F + 1);
        if (d0     <= GRID_F) v0 = base[d0];
        if (d0 + 1 <= GRID_F) v1 = base[d0 + 1];
    }
    float l0, l1;
    uint32_t hp = pack_hi(v0, v1, l0, l1);
    uint32_t lp = pack_lo(l0, l1);
    size_t base = ((size_t)(nb * NCH_L + c)) * (2 * TILE_B) + p * KSTR_B + n;
    g_WtL32[base]          = hp;
    g_WtL32[base + TILE_B] = lp;
}

// -------- CSR build --------
__global__ void k_zero_cnt() {
    int i = blockIdx.x * 256 + threadIdx.x;
    if (i < N_NODES) g_cnt[i] = 0;
}
__global__ void k_hist(const int* __restrict__ dst) {
    int e = blockIdx.x * 256 + threadIdx.x;
    if (e < N_EDGES) atomicAdd(&g_cnt[dst[e]], 1);
}
__global__ void k_scan() {
    __shared__ int s[1024];
    int tid = threadIdx.x;
    const int CH = 20;
    int base = tid * CH;
    int sum = 0;
    for (int j = 0; j < CH; j++) { int idx = base + j; if (idx < N_NODES) sum += g_cnt[idx]; }
    s[tid] = sum; __syncthreads();
    for (int d = 1; d < 1024; d <<= 1) {
        int v = (tid >= d) ? s[tid - d] : 0;
        __syncthreads();
        s[tid] += v;
        __syncthreads();
    }
    int run = (tid > 0) ? s[tid - 1] : 0;
    for (int j = 0; j < CH; j++) {
        int idx = base + j;
        if (idx < N_NODES) { g_off[idx] = run; g_cur[idx] = run; run += g_cnt[idx]; }
    }
    if (tid == 1023) g_off[N_NODES] = s[1023];
}
__global__ void k_scatter(const int* __restrict__ src, const int* __restrict__ dst) {
    int e = blockIdx.x * 256 + threadIdx.x;
    if (e < N_EDGES) {
        int pos = atomicAdd(&g_cur[dst[e]], 1);
        g_csrc[pos] = src[e];
    }
}

// -------- edge aggregation (CSR gather, no atomics) --------
__global__ void k_agg() {
    int node = blockIdx.x * 4 + (threadIdx.x >> 6);
    int lane = threadIdx.x & 63;
    float4 acc = make_float4(0.f, 0.f, 0.f, 0.f);
    if (node < N_NODES) {
        int lo = g_off[node], hi = g_off[node + 1];
        const float4* H4 = (const float4*)g_H;
        for (int e = lo; e < hi; e++) {
            int sN = g_csrc[e];
            float4 v = H4[sN * 64 + lane];
            acc.x += v.x; acc.y += v.y; acc.z += v.z; acc.w += v.w;
        }
    }
    ((float4*)g_AGG)[node * 64 + lane] = acc;
}

// -------- fp16 split-2 3-term mma.sync GEMM, fused activations --------
// CTA 64x128, BK=32 (16 kpairs), 4 warps (warp tile 64x32), occ 4 for wave balance.
template <int MODE>
__global__ void __launch_bounds__(128, 4) k_mma(const float* __restrict__ X, int layer) {
    __shared__ uint32_t sm[2 * TILE_A + 2 * TILE_B];
    uint32_t* As_hi = sm;
    uint32_t* As_lo = sm + TILE_A;
    uint32_t* Bs_hi = sm + 2 * TILE_A;
    uint32_t* Bs_lo = sm + 2 * TILE_A + TILE_B;

    const int NCH  = (MODE == 0) ? NCH_L : NCH_F;
    const int srcw = (MODE == 0) ? IN_FEAT : HIDDEN;
    const float* A = (MODE == 0) ? X : g_AGG;
    const uint32_t* Bsrc = (MODE == 0)
        ? (g_WtL32 + (size_t)(blockIdx.y * NCH_L) * (2 * TILE_B))
        : (g_WtF32 + (size_t)((layer * 2 + blockIdx.y) * NCH_F) * (2 * TILE_B));

    int tid  = threadIdx.x;
    int lane = tid & 31;
    int wid  = tid >> 5;        // 0..3
    int wn = wid * 32;          // warp n offset; warp m spans full 64
    int mb = blockIdx.x * 64;
    int ob = blockIdx.y * 128;

    int row = tid & 63;         // A-fill row
    int f2  = (tid >> 6) * 2;   // A-fill feature pair (0-1 or 2-3)
    int gr  = mb + row;

    float d[4][4][4];
    #pragma unroll
    for (int mf = 0; mf < 4; mf++)
        #pragma unroll
        for (int nf = 0; nf < 4; nf++)
            #pragma unroll
            for (int q = 0; q < 4; q++) d[mf][nf][q] = 0.f;

    for (int c = 0; c < NCH; c++) {
        __syncthreads();
        // ---- A fill: 2 (row, feature) activations per thread, split + pack ----
        #pragma unroll
        for (int ff = 0; ff < 2; ff++) {
            int lf = f2 + ff;
            float a = 0.f;
            if (MODE == 1 || gr < N_NODES) a = A[(size_t)gr * srcw + c * 4 + lf];
            float vals[8];
            if (MODE == 0) {
                float pw = 1.f;
                #pragma unroll
                for (int v = 0; v < 5; v++) { vals[v] = pw; pw *= a; }
                vals[5] = 0.f; vals[6] = 0.f; vals[7] = 0.f;
            } else {
                float s1, c1;
                sincosf(a, &s1, &c1);
                float ck = c1, sk = s1;
                vals[0] = ck; vals[4] = sk;
                #pragma unroll
                for (int g = 1; g < 4; g++) {
                    float c2 = ck * c1 - sk * s1;
                    float s2 = sk * c1 + ck * s1;
                    ck = c2; sk = s2;
                    vals[g] = ck; vals[4 + g] = sk;
                }
            }
            #pragma unroll
            for (int t = 0; t < 4; t++) {
                float l0, l1;
                uint32_t hp = pack_hi(vals[2 * t], vals[2 * t + 1], l0, l1);
                uint32_t lp = pack_lo(l0, l1);
                int off = (lf * 4 + t) * KSTR_A + row;
                As_hi[off] = hp;
                As_lo[off] = lp;
            }
        }
        // ---- B fill: contiguous float4 copy (hi + lo tiles adjacent) ----
        {
            const float4* sp = (const float4*)(Bsrc + (size_t)c * (2 * TILE_B));
            float4* dp = (float4*)Bs_hi;   // Bs_hi/Bs_lo contiguous
            #pragma unroll
            for (int q = 0; q < 9; q++) {
                int p = tid + q * 128;
                if (p < 2 * TILE_B / 4) dp[p] = sp[p];
            }
        }
        __syncthreads();
        // ---- compute: 2 k16 steps, 3 mma terms each ----
        #pragma unroll
        for (int s = 0; s < 2; s++) {
            int kp = s * 8 + (lane & 3);
            int aoff = kp * KSTR_A + (lane >> 2);
            int boff = kp * KSTR_B + wn + (lane >> 2);
            uint32_t ah[4][4], al[4][4], bh[4][2], bl[4][2];
            #pragma unroll
            for (int mf = 0; mf < 4; mf++) {
                ah[mf][0] = As_hi[aoff + mf * 16];
                ah[mf][1] = As_hi[aoff + mf * 16 + 8];
                ah[mf][2] = As_hi[aoff + 4 * KSTR_A + mf * 16];
                ah[mf][3] = As_hi[aoff + 4 * KSTR_A + mf * 16 + 8];
                al[mf][0] = As_lo[aoff + mf * 16];
                al[mf][1] = As_lo[aoff + mf * 16 + 8];
                al[mf][2] = As_lo[aoff + 4 * KSTR_A + mf * 16];
                al[mf][3] = As_lo[aoff + 4 * KSTR_A + mf * 16 + 8];
            }
            #pragma unroll
            for (int nf = 0; nf < 4; nf++) {
                bh[nf][0] = Bs_hi[boff + nf * 8];
                bh[nf][1] = Bs_hi[boff + 4 * KSTR_B + nf * 8];
                bl[nf][0] = Bs_lo[boff + nf * 8];
                bl[nf][1] = Bs_lo[boff + 4 * KSTR_B + nf * 8];
            }
            #pragma unroll
            for (int mf = 0; mf < 4; mf++)
                #pragma unroll
                for (int nf = 0; nf < 4; nf++) {
                    mma_f16(d[mf][nf], al[mf], bh[nf]);   // lo*hi
                    mma_f16(d[mf][nf], ah[mf], bl[nf]);   // hi*lo
                    mma_f16(d[mf][nf], ah[mf], bh[nf]);   // hi*hi
                }
        }
    }

    // ---- epilogue: residual + leaky relu (MODE 1) ----
    int r0 = lane >> 2;
    int c0 = 2 * (lane & 3);
    #pragma unroll
    for (int mf = 0; mf < 4; mf++) {
        #pragma unroll
        for (int half = 0; half < 2; half++) {
            int rg = mb + mf * 16 + r0 + half * 8;
            float* Hrow = g_H + (size_t)rg * HIDDEN + ob + wn + c0;
            #pragma unroll
            for (int nf = 0; nf < 4; nf++) {
                float vx = d[mf][nf][half * 2];
                float vy = d[mf][nf][half * 2 + 1];
                float2* p = (float2*)(Hrow + nf * 8);
                if (MODE == 1) {
                    float2 h0 = *p;
                    vx += h0.x; vy += h0.y;
                    vx = (vx > 0.f) ? vx : vx * NEG_SLOPE;
                    vy = (vy > 0.f) ? vy : vy * NEG_SLOPE;
                }
                *p = make_float2(vx, vy);
            }
        }
    }
}

// -------- pooling + readout --------
__device__ __forceinline__ int lbound(const int* a, int n, int v) {
    int lo = 0, hi = n;
    while (lo < hi) { int m = (lo + hi) >> 1; if (a[m] < v) lo = m + 1; else hi = m; }
    return lo;
}
__global__ void k_pool(const int* __restrict__ gid, const float* __restrict__ Wout,
                       const float* __restrict__ bout, float* __restrict__ out) {
    int g = blockIdx.x;
    int f = threadIdx.x;
    int lo = lbound(gid, N_NODES, g);
    int hi = lbound(gid, N_NODES, g + 1);
    float acc = 0.f;
    for (int n = lo; n < hi; n++) acc += g_H[(size_t)n * HIDDEN + f];
    float cnt = (float)(hi - lo);
    float y = acc / fmaxf(cnt, 1.f);
    float contrib = Wout[f * 2] + Wout[f * 2 + 1] * y;
    __shared__ float red[256];
    red[f] = contrib; __syncthreads();
    for (int st = 128; st > 0; st >>= 1) {
        if (f < st) red[f] += red[f + st];
        __syncthreads();
    }
    if (f == 0) out[g] = 1.f / (1.f + expf(-(red[0] + bout[0])));
}

// -------- launch --------
extern "C" void kernel_launch(void* const* d_in, const int* in_sizes, int n_in,
                              void* d_out, int out_size) {
    const float* h      = (const float*)d_in[0];
    const int*   src    = (const int*)  d_in[1];
    const int*   dst    = (const int*)  d_in[2];
    const int*   gid    = (const int*)  d_in[3];
    const float* W_line = (const float*)d_in[4];
    const float* fc     = (const float*)d_in[5];
    const float* W_out  = (const float*)d_in[6];
    const float* b_out  = (const float*)d_in[7];
    float* out = (float*)d_out;

    k_prep_line   <<<(2 * NCH_L * TILE_B + 255) / 256, 256>>>(W_line);
    k_prep_fourier<<<(3 * 2 * NCH_F * TILE_B + 255) / 256, 256>>>(fc);

    k_zero_cnt<<<(N_NODES + 255) / 256, 256>>>();
    k_hist    <<<(N_EDGES + 255) / 256, 256>>>(dst);
    k_scan    <<<1, 1024>>>();
    k_scatter <<<(N_EDGES + 255) / 256, 256>>>(src, dst);

    dim3 gg(MT, 2);
    k_mma<0><<<gg, 128>>>(h, 0);
    for (int l = 0; l < 3; l++) {
        k_agg  <<<MPAD / 4, 256>>>();
        k_mma<1><<<gg, 128>>>(nullptr, l);
    }
    k_pool<<<N_GRAPHS, 256>>>(gid, W_out, b_out, out);
}

// round 10
// speedup vs baseline: 2.7845x; 1.1450x over previous
#include <cuda_runtime.h>
#include <cuda_fp16.h>
#include <math.h>
#include <stdint.h>

#define N_NODES 20000
#define MPAD    20032          // multiple of 64
#define MT      (MPAD / 64)    // 313 M-tiles
#define N_EDGES 320000
#define N_GRAPHS 64
#define IN_FEAT 64
#define HIDDEN  256
#define GRID_F  4
#define NEG_SLOPE 0.01f

#define NCH_F 64               // fourier K=2048 -> 64 chunks of 32
#define NCH_L 10               // line  K=320 -> 10 chunks of 32 (exact)
#define KSTR_A 72              // A row stride in u32 (mod 32 = 8 -> conflict-free)
#define KSTR_B 136             // B row stride in u32 (mod 32 = 8)
#define TILE_A (16 * KSTR_A)   // 1152 u32
#define TILE_B (16 * KSTR_B)   // 2176 u32
#define BUFU32 (2 * TILE_A + 2 * TILE_B)   // 6656 u32 per pipeline buffer
#define SM_BYTES (2 * BUFU32 * 4)          // 53248 B dynamic smem

// -------- device scratch --------
__device__ __align__(16) float  g_H [MPAD * HIDDEN];
__device__ __align__(16) float2 g_CS[MPAD * HIDDEN];   // (cos, sin) of aggregated value
__device__ __align__(16) uint32_t g_WtF32[3 * 2 * NCH_F * 2 * TILE_B];
__device__ __align__(16) uint32_t g_WtL32[2 * NCH_L * 2 * TILE_B];
__device__ int g_cnt [N_NODES];
__device__ int g_off [N_NODES + 1];
__device__ int g_cur [N_NODES];
__device__ int g_csrc[N_EDGES];

// -------- helpers --------
__device__ __forceinline__ uint32_t s2u(const void* p) {
    uint32_t a;
    asm("{ .reg .u64 t; cvta.to.shared.u64 t, %1; cvt.u32.u64 %0, t; }" : "=r"(a) : "l"(p));
    return a;
}
__device__ __forceinline__ uint32_t pack_hi(float v0, float v1, float& l0, float& l1) {
    __half h0 = __float2half_rn(v0), h1 = __float2half_rn(v1);
    l0 = v0 - __half2float(h0);
    l1 = v1 - __half2float(h1);
    return (uint32_t)__half_as_ushort(h0) | ((uint32_t)__half_as_ushort(h1) << 16);
}
__device__ __forceinline__ uint32_t pack_lo(float l0, float l1) {
    return (uint32_t)__half_as_ushort(__float2half_rn(l0))
         | ((uint32_t)__half_as_ushort(__float2half_rn(l1)) << 16);
}
__device__ __forceinline__ void mma_f16(float* d, const uint32_t* a, const uint32_t* b) {
    asm volatile(
        "mma.sync.aligned.m16n8k16.row.col.f32.f16.f16.f32 "
        "{%0,%1,%2,%3}, {%4,%5,%6,%7}, {%8,%9}, {%0,%1,%2,%3};"
        : "+f"(d[0]), "+f"(d[1]), "+f"(d[2]), "+f"(d[3])
        : "r"(a[0]), "r"(a[1]), "r"(a[2]), "r"(a[3]), "r"(b[0]), "r"(b[1]));
}
#define CP_ASYNC16(saddr, gptr) \
    asm volatile("cp.async.cg.shared.global [%0], [%1], 16;" :: "r"(saddr), "l"(gptr) : "memory")
#define CP_COMMIT() asm volatile("cp.async.commit_group;" ::: "memory")
#define CP_WAIT0()  asm volatile("cp.async.wait_group 0;" ::: "memory")

// -------- weight prep --------
__global__ void k_prep_fourier(const float* __restrict__ F) {
    int idx = blockIdx.x * 256 + threadIdx.x;
    if (idx >= 3 * 2 * NCH_F * TILE_B) return;
    int n = idx % KSTR_B;
    int t = idx / KSTR_B;
    int p = t & 15; t >>= 4;
    int c = t % NCH_F; t /= NCH_F;
    int nb = t & 1;
    int l  = t >> 1;
    float v0 = 0.f, v1 = 0.f;
    if (n < 128) {
        int lf = p >> 2, tq = p & 3;
        int i  = c * 4 + lf;
        int s0 = tq >> 1;
        int g0 = (tq & 1) * 2;
        int ng = nb * 128 + n;
        const float* base = F + (((size_t)(l * 2 + s0) * HIDDEN + ng) * HIDDEN + i) * GRID_F;
        v0 = base[g0];
        v1 = base[g0 + 1];
    }
    float l0, l1;
    uint32_t hp = pack_hi(v0, v1, l0, l1);
    uint32_t lp = pack_lo(l0, l1);
    size_t base = ((size_t)((l * 2 + nb) * NCH_F + c)) * (2 * TILE_B) + p * KSTR_B + n;
    g_WtF32[base]          = hp;
    g_WtF32[base + TILE_B] = lp;
}
// Line: exact K=320. kk in chunk -> global k = c*32 + kk, i = k/5, d = k%5.
__global__ void k_prep_line(const float* __restrict__ W) {
    int idx = blockIdx.x * 256 + threadIdx.x;
    if (idx >= 2 * NCH_L * TILE_B) return;
    int n = idx % KSTR_B;
    int t = idx / KSTR_B;
    int p = t & 15; t >>= 4;
    int c = t % NCH_L;
    int nb = t / NCH_L;
    float v0 = 0.f, v1 = 0.f;
    if (n < 128) {
        int ng = nb * 128 + n;
        int k0 = c * 32 + 2 * p;
        int i0 = k0 / 5, d0 = k0 - 5 * i0;
        int k1 = k0 + 1;
        int i1 = k1 / 5, d1 = k1 - 5 * i1;
        v0 = W[((size_t)ng * IN_FEAT + i0) * (GRID_F + 1) + d0];
        v1 = W[((size_t)ng * IN_FEAT + i1) * (GRID_F + 1) + d1];
    }
    float l0, l1;
    uint32_t hp = pack_hi(v0, v1, l0, l1);
    uint32_t lp = pack_lo(l0, l1);
    size_t base = ((size_t)(nb * NCH_L + c)) * (2 * TILE_B) + p * KSTR_B + n;
    g_WtL32[base]          = hp;
    g_WtL32[base + TILE_B] = lp;
}

// -------- CSR build --------
__global__ void k_zero_cnt() {
    int i = blockIdx.x * 256 + threadIdx.x;
    if (i < N_NODES) g_cnt[i] = 0;
}
__global__ void k_hist(const int* __restrict__ dst) {
    int e = blockIdx.x * 256 + threadIdx.x;
    if (e < N_EDGES) atomicAdd(&g_cnt[dst[e]], 1);
}
__global__ void k_scan() {
    __shared__ int s[1024];
    int tid = threadIdx.x;
    const int CH = 20;
    int base = tid * CH;
    int sum = 0;
    for (int j = 0; j < CH; j++) { int idx = base + j; if (idx < N_NODES) sum += g_cnt[idx]; }
    s[tid] = sum; __syncthreads();
    for (int d = 1; d < 1024; d <<= 1) {
        int v = (tid >= d) ? s[tid - d] : 0;
        __syncthreads();
        s[tid] += v;
        __syncthreads();
    }
    int run = (tid > 0) ? s[tid - 1] : 0;
    for (int j = 0; j < CH; j++) {
        int idx = base + j;
        if (idx < N_NODES) { g_off[idx] = run; g_cur[idx] = run; run += g_cnt[idx]; }
    }
    if (tid == 1023) g_off[N_NODES] = s[1023];
}
__global__ void k_scatter(const int* __restrict__ src, const int* __restrict__ dst) {
    int e = blockIdx.x * 256 + threadIdx.x;
    if (e < N_EDGES) {
        int pos = atomicAdd(&g_cur[dst[e]], 1);
        g_csrc[pos] = src[e];
    }
}

// -------- edge aggregation + sincos (CSR gather, no atomics) --------
__global__ void k_agg() {
    int node = blockIdx.x * 4 + (threadIdx.x >> 6);
    int lane = threadIdx.x & 63;
    float4 acc = make_float4(0.f, 0.f, 0.f, 0.f);
    if (node < N_NODES) {
        int lo = g_off[node], hi = g_off[node + 1];
        const float4* H4 = (const float4*)g_H;
        int e = lo;
        for (; e + 1 < hi; e += 2) {
            int s0 = g_csrc[e], s1 = g_csrc[e + 1];
            float4 v0 = H4[s0 * 64 + lane];
            float4 v1 = H4[s1 * 64 + lane];
            acc.x += v0.x; acc.y += v0.y; acc.z += v0.z; acc.w += v0.w;
            acc.x += v1.x; acc.y += v1.y; acc.z += v1.z; acc.w += v1.w;
        }
        if (e < hi) {
            int s0 = g_csrc[e];
            float4 v0 = H4[s0 * 64 + lane];
            acc.x += v0.x; acc.y += v0.y; acc.z += v0.z; acc.w += v0.w;
        }
    }
    float2 cs0, cs1, cs2, cs3;
    sincosf(acc.x, &cs0.y, &cs0.x);
    sincosf(acc.y, &cs1.y, &cs1.x);
    sincosf(acc.z, &cs2.y, &cs2.x);
    sincosf(acc.w, &cs3.y, &cs3.x);
    float4* dst4 = (float4*)(g_CS + (size_t)node * HIDDEN + lane * 4);
    dst4[0] = make_float4(cs0.x, cs0.y, cs1.x, cs1.y);
    dst4[1] = make_float4(cs2.x, cs2.y, cs3.x, cs3.y);
}

// -------- A-tile fill helpers --------
// MODE1: from (c1,s1) pair, fill kpairs lf*4..lf*4+3 at row.
__device__ __forceinline__ void fillA1(uint32_t* Ah, uint32_t* Al, float2 cs,
                                       int lf, int row) {
    float c1 = cs.x, s1 = cs.y;
    float vals[8];
    vals[0] = c1; vals[4] = s1;
    float ck = c1, sk = s1;
    #pragma unroll
    for (int g = 1; g < 4; g++) {
        float c2 = ck * c1 - sk * s1;
        float s2 = sk * c1 + ck * s1;
        ck = c2; sk = s2;
        vals[g] = ck; vals[4 + g] = sk;
    }
    #pragma unroll
    for (int t = 0; t < 4; t++) {
        float l0, l1;
        uint32_t hp = pack_hi(vals[2 * t], vals[2 * t + 1], l0, l1);
        uint32_t lp = pack_lo(l0, l1);
        int off = (lf * 4 + t) * KSTR_A + row;
        Ah[off] = hp;
        Al[off] = lp;
    }
}
__device__ __forceinline__ float powd(float x, int dd) {
    float x2 = x * x;
    float r = 1.f;
    if (dd == 1) r = x;
    else if (dd == 2) r = x2;
    else if (dd == 3) r = x2 * x;
    else if (dd == 4) r = x2 * x2;
    return r;
}
// MODE0: thread fills kpairs plane*8..plane*8+7 at row; k = c*32+2p -> x_{k/5}^{k%5}
__device__ __forceinline__ void fillA0(uint32_t* Ah, uint32_t* Al, const float* __restrict__ X,
                                       int c, int plane, int row, int gr) {
    #pragma unroll
    for (int j = 0; j < 8; j++) {
        int p = plane * 8 + j;
        int k0 = c * 32 + 2 * p;
        int i0 = k0 / 5, d0 = k0 - 5 * i0;
        int k1 = k0 + 1;
        int i1 = k1 / 5, d1 = k1 - 5 * i1;
        float x0 = (gr < N_NODES) ? X[(size_t)gr * IN_FEAT + i0] : 0.f;
        float x1 = (gr < N_NODES) ? X[(size_t)gr * IN_FEAT + i1] : 0.f;
        float v0 = powd(x0, d0);
        float v1 = powd(x1, d1);
        float l0, l1;
        uint32_t hp = pack_hi(v0, v1, l0, l1);
        uint32_t lp = pack_lo(l0, l1);
        int off = p * KSTR_A + row;
        Ah[off] = hp;
        Al[off] = lp;
    }
}

// -------- fp16 split-2 3-term mma.sync GEMM, cp.async double-buffered --------
// CTA 64x128, BK=32, 4 warps (warp tile 64x32), occ 4, dynamic smem 53 KB.
template <int MODE>
__global__ void __launch_bounds__(128, 4) k_mma(const float* __restrict__ X, int layer) {
    extern __shared__ uint32_t sm[];
    uint32_t smb = s2u(sm);

    const int NCH = (MODE == 0) ? NCH_L : NCH_F;
    const uint32_t* Bsrc = (MODE == 0)
        ? (g_WtL32 + (size_t)(blockIdx.y * NCH_L) * (2 * TILE_B))
        : (g_WtF32 + (size_t)((layer * 2 + blockIdx.y) * NCH_F) * (2 * TILE_B));

    int tid  = threadIdx.x;
    int lane = tid & 31;
    int wid  = tid >> 5;
    int wn = wid * 32;
    int mb = blockIdx.x * 64;
    int ob = blockIdx.y * 128;

    int row   = tid & 63;
    int plane = tid >> 6;       // 0/1
    int f2    = plane * 2;      // MODE1 feature pair base
    int gr    = mb + row;

    float d[4][4][4];
    #pragma unroll
    for (int mf = 0; mf < 4; mf++)
        #pragma unroll
        for (int nf = 0; nf < 4; nf++)
            #pragma unroll
            for (int q = 0; q < 4; q++) d[mf][nf][q] = 0.f;

    // ---- prologue: fill chunk 0 into buffer 0 ----
    {
        uint32_t* Ah = sm;
        uint32_t* Al = sm + TILE_A;
        if (MODE == 1) {
            const float2* csrow = g_CS + (size_t)gr * HIDDEN;
            fillA1(Ah, Al, csrow[f2],     f2,     row);
            fillA1(Ah, Al, csrow[f2 + 1], f2 + 1, row);
        } else {
            fillA0(Ah, Al, X, 0, plane, row, gr);
        }
        uint32_t bdst = smb + (2 * TILE_A) * 4;
        const float4* sp = (const float4*)Bsrc;
        #pragma unroll
        for (int q = 0; q < 9; q++) {
            int p = tid + q * 128;
            if (p < 2 * TILE_B / 4) CP_ASYNC16(bdst + p * 16, sp + p);
        }
        CP_COMMIT();
        CP_WAIT0();
        __syncthreads();
    }

    for (int c = 0; c < NCH; c++) {
        int cur = c & 1, nxt = cur ^ 1;
        bool hn = (c + 1) < NCH;
        // 1. stage next A inputs (LDG fires early; latency hidden by compute)
        float2 ncs0, ncs1;
        if (MODE == 1 && hn) {
            const float2* csrow = g_CS + (size_t)gr * HIDDEN + (c + 1) * 4;
            ncs0 = csrow[f2];
            ncs1 = csrow[f2 + 1];
        }
        // 2. stream next B via cp.async (fire and forget)
        if (hn) {
            uint32_t bdst = smb + (nxt * BUFU32 + 2 * TILE_A) * 4;
            const float4* sp = (const float4*)(Bsrc + (size_t)(c + 1) * (2 * TILE_B));
            #pragma unroll
            for (int q = 0; q < 9; q++) {
                int p = tid + q * 128;
                if (p < 2 * TILE_B / 4) CP_ASYNC16(bdst + p * 16, sp + p);
            }
        }
        CP_COMMIT();
        // 3. compute chunk c
        {
            uint32_t* As_hi = sm + cur * BUFU32;
            uint32_t* As_lo = As_hi + TILE_A;
            uint32_t* Bs_hi = As_hi + 2 * TILE_A;
            uint32_t* Bs_lo = Bs_hi + TILE_B;
            #pragma unroll
            for (int s = 0; s < 2; s++) {
                int kp = s * 8 + (lane & 3);
                int aoff = kp * KSTR_A + (lane >> 2);
                int boff = kp * KSTR_B + wn + (lane >> 2);
                uint32_t ah[4][4], al[4][4], bh[4][2], bl[4][2];
                #pragma unroll
                for (int mf = 0; mf < 4; mf++) {
                    ah[mf][0] = As_hi[aoff + mf * 16];
                    ah[mf][1] = As_hi[aoff + mf * 16 + 8];
                    ah[mf][2] = As_hi[aoff + 4 * KSTR_A + mf * 16];
                    ah[mf][3] = As_hi[aoff + 4 * KSTR_A + mf * 16 + 8];
                    al[mf][0] = As_lo[aoff + mf * 16];
                    al[mf][1] = As_lo[aoff + mf * 16 + 8];
                    al[mf][2] = As_lo[aoff + 4 * KSTR_A + mf * 16];
                    al[mf][3] = As_lo[aoff + 4 * KSTR_A + mf * 16 + 8];
                }
                #pragma unroll
                for (int nf = 0; nf < 4; nf++) {
                    bh[nf][0] = Bs_hi[boff + nf * 8];
                    bh[nf][1] = Bs_hi[boff + 4 * KSTR_B + nf * 8];
                    bl[nf][0] = Bs_lo[boff + nf * 8];
                    bl[nf][1] = Bs_lo[boff + 4 * KSTR_B + nf * 8];
                }
                #pragma unroll
                for (int mf = 0; mf < 4; mf++)
                    #pragma unroll
                    for (int nf = 0; nf < 4; nf++) {
                        mma_f16(d[mf][nf], al[mf], bh[nf]);
                        mma_f16(d[mf][nf], ah[mf], bl[nf]);
                        mma_f16(d[mf][nf], ah[mf], bh[nf]);
                    }
            }
        }
        // 4. fill next A tile (inputs already in regs / L1)
        if (hn) {
            uint32_t* Ah = sm + nxt * BUFU32;
            uint32_t* Al = Ah + TILE_A;
            if (MODE == 1) {
                fillA1(Ah, Al, ncs0, f2,     row);
                fillA1(Ah, Al, ncs1, f2 + 1, row);
            } else {
                fillA0(Ah, Al, X, c + 1, plane, row, gr);
            }
        }
        // 5. barrier: B(c+1) landed, A(c+1) visible, compute(c) reads done
        CP_WAIT0();
        __syncthreads();
    }

    // ---- epilogue: residual + leaky relu (MODE 1) ----
    int r0 = lane >> 2;
    int c0 = 2 * (lane & 3);
    #pragma unroll
    for (int mf = 0; mf < 4; mf++) {
        #pragma unroll
        for (int half = 0; half < 2; half++) {
            int rg = mb + mf * 16 + r0 + half * 8;
            float* Hrow = g_H + (size_t)rg * HIDDEN + ob + wn + c0;
            #pragma unroll
            for (int nf = 0; nf < 4; nf++) {
                float vx = d[mf][nf][half * 2];
                float vy = d[mf][nf][half * 2 + 1];
                float2* p = (float2*)(Hrow + nf * 8);
                if (MODE == 1) {
                    float2 h0 = *p;
                    vx += h0.x; vy += h0.y;
                    vx = (vx > 0.f) ? vx : vx * NEG_SLOPE;
                    vy = (vy > 0.f) ? vy : vy * NEG_SLOPE;
                }
                *p = make_float2(vx, vy);
            }
        }
    }
}

// -------- pooling + readout --------
__device__ __forceinline__ int lbound(const int* a, int n, int v) {
    int lo = 0, hi = n;
    while (lo < hi) { int m = (lo + hi) >> 1; if (a[m] < v) lo = m + 1; else hi = m; }
    return lo;
}
__global__ void k_pool(const int* __restrict__ gid, const float* __restrict__ Wout,
                       const float* __restrict__ bout, float* __restrict__ out) {
    int g = blockIdx.x;
    int f = threadIdx.x;
    int lo = lbound(gid, N_NODES, g);
    int hi = lbound(gid, N_NODES, g + 1);
    float acc = 0.f;
    for (int n = lo; n < hi; n++) acc += g_H[(size_t)n * HIDDEN + f];
    float cnt = (float)(hi - lo);
    float y = acc / fmaxf(cnt, 1.f);
    float contrib = Wout[f * 2] + Wout[f * 2 + 1] * y;
    __shared__ float red[256];
    red[f] = contrib; __syncthreads();
    for (int st = 128; st > 0; st >>= 1) {
        if (f < st) red[f] += red[f + st];
        __syncthreads();
    }
    if (f == 0) out[g] = 1.f / (1.f + expf(-(red[0] + bout[0])));
}

// -------- launch --------
extern "C" void kernel_launch(void* const* d_in, const int* in_sizes, int n_in,
                              void* d_out, int out_size) {
    const float* h      = (const float*)d_in[0];
    const int*   src    = (const int*)  d_in[1];
    const int*   dst    = (const int*)  d_in[2];
    const int*   gid    = (const int*)  d_in[3];
    const float* W_line = (const float*)d_in[4];
    const float* fc     = (const float*)d_in[5];
    const float* W_out  = (const float*)d_in[6];
    const float* b_out  = (const float*)d_in[7];
    float* out = (float*)d_out;

    static int smem_set = 0;
    if (!smem_set) {
        cudaFuncSetAttribute(k_mma<0>, cudaFuncAttributeMaxDynamicSharedMemorySize, SM_BYTES);
        cudaFuncSetAttribute(k_mma<1>, cudaFuncAttributeMaxDynamicSharedMemorySize, SM_BYTES);
        smem_set = 1;
    }

    k_prep_line   <<<(2 * NCH_L * TILE_B + 255) / 256, 256>>>(W_line);
    k_prep_fourier<<<(3 * 2 * NCH_F * TILE_B + 255) / 256, 256>>>(fc);

    k_zero_cnt<<<(N_NODES + 255) / 256, 256>>>();
    k_hist    <<<(N_EDGES + 255) / 256, 256>>>(dst);
    k_scan    <<<1, 1024>>>();
    k_scatter <<<(N_EDGES + 255) / 256, 256>>>(src, dst);

    dim3 gg(MT, 2);
    k_mma<0><<<gg, 128, SM_BYTES>>>(h, 0);
    for (int l = 0; l < 3; l++) {
        k_agg  <<<MPAD / 4, 256>>>();
        k_mma<1><<<gg, 128, SM_BYTES>>>(nullptr, l);
    }
    k_pool<<<N_GRAPHS, 256>>>(gid, W_out, b_out, out);
}